// round 7
// baseline (speedup 1.0000x reference)
#include <cuda_runtime.h>
#include <cuda_fp16.h>
#include <cstdint>

#define NPIX 4096
#define CIN  256
#define CQK  64
#define BATCH 4
#define NCH  (NPIX / 64)

// ------------------------- device scratch ----------------------------------
__device__ float  g_w2[CIN * CIN];
__device__ __half g_wc[384 * CIN];                   // [wq(64); wk(64); w2(256)] fp16
__device__ float  g_bc[384];                         // [bq; bk; b2]
__device__ __half g_q[(size_t)BATCH * NPIX * CQK];   // [b][n][o]
__device__ __half g_k[(size_t)BATCH * NPIX * CQK];   // [b][m][o]
__device__ __half g_v[(size_t)BATCH * CIN * NPIX];   // [b][c][n]

// ------------------------- helpers -----------------------------------------
__device__ __forceinline__ uint32_t smem_u32(const void* p) {
    uint32_t a;
    asm("{ .reg .u64 t; cvta.to.shared.u64 t, %1; cvt.u32.u64 %0, t; }" : "=r"(a) : "l"(p));
    return a;
}
__device__ __forceinline__ void ldsm_x4(uint32_t a[4], uint32_t addr) {
    asm volatile("ldmatrix.sync.aligned.m8n8.x4.shared.b16 {%0,%1,%2,%3}, [%4];"
                 : "=r"(a[0]), "=r"(a[1]), "=r"(a[2]), "=r"(a[3]) : "r"(addr));
}
__device__ __forceinline__ void ldsm_x2(uint32_t a[2], uint32_t addr) {
    asm volatile("ldmatrix.sync.aligned.m8n8.x2.shared.b16 {%0,%1}, [%2];"
                 : "=r"(a[0]), "=r"(a[1]) : "r"(addr));
}
__device__ __forceinline__ void ldsm_x4_t(uint32_t a[4], uint32_t addr) {
    asm volatile("ldmatrix.sync.aligned.m8n8.x4.trans.shared.b16 {%0,%1,%2,%3}, [%4];"
                 : "=r"(a[0]), "=r"(a[1]), "=r"(a[2]), "=r"(a[3]) : "r"(addr));
}
__device__ __forceinline__ void ldsm_x2_t(uint32_t a[2], uint32_t addr) {
    asm volatile("ldmatrix.sync.aligned.m8n8.x2.trans.shared.b16 {%0,%1}, [%2];"
                 : "=r"(a[0]), "=r"(a[1]) : "r"(addr));
}
__device__ __forceinline__ void mma16816(float d[4], const uint32_t a[4], const uint32_t b[2]) {
    asm volatile(
        "mma.sync.aligned.m16n8k16.row.col.f32.f16.f16.f32 "
        "{%0,%1,%2,%3}, {%4,%5,%6,%7}, {%8,%9}, {%0,%1,%2,%3};"
        : "+f"(d[0]), "+f"(d[1]), "+f"(d[2]), "+f"(d[3])
        : "r"(a[0]), "r"(a[1]), "r"(a[2]), "r"(a[3]), "r"(b[0]), "r"(b[1]));
}
#define CP_ASYNC16(dst, src) \
    asm volatile("cp.async.cg.shared.global [%0], [%1], 16;" :: "r"(dst), "l"(src))
#define CP_COMMIT() asm volatile("cp.async.commit_group;" ::: "memory")
#define CP_WAIT(n)  asm volatile("cp.async.wait_group %0;" :: "n"(n) : "memory")

__device__ __forceinline__ float eluf(float x) { return x > 0.f ? x : (__expf(x) - 1.f); }
__device__ __forceinline__ unsigned pk2(float a, float b) {
    __half2 h = __floats2half2_rn(a, b);
    return *(unsigned*)&h;
}

// ------------------------- weight folding / packing ------------------------
__global__ void fold_w(const float* __restrict__ wg, const float* __restrict__ wv,
                       float* __restrict__ w2) {
    int o = blockIdx.x, j = threadIdx.x;
    float s = 0.f;
    for (int c = 0; c < CIN; c++) s += wg[o * CIN + c] * wv[c * CIN + j];
    w2[o * CIN + j] = s;
}
__global__ void pack_weights(const float* __restrict__ wq, const float* __restrict__ wk,
                             const float* __restrict__ w2, const float* __restrict__ bq,
                             const float* __restrict__ bk, const float* __restrict__ wg,
                             const float* __restrict__ bv, __half* __restrict__ Wc,
                             float* __restrict__ bc) {
    int r = blockIdx.x, c = threadIdx.x;
    const float* src = r < 64 ? wq + r * CIN : (r < 128 ? wk + (r - 64) * CIN : w2 + (r - 128) * CIN);
    Wc[r * CIN + c] = __float2half(src[c]);
    if (c == 0) {
        if (r < 64) bc[r] = bq[r];
        else if (r < 128) bc[r] = bk[r - 64];
        else {
            float s = 0.f;
            int o = r - 128;
            for (int cc = 0; cc < CIN; cc++) s += wg[o * CIN + cc] * bv[cc];
            bc[r] = s;
        }
    }
}

// ----------------- fused QKV projection (HMMA, fp16) -----------------------
#define XST 136
#define WST 72

__global__ __launch_bounds__(256) void proj_qkv(
    const float* __restrict__ X, const __half* __restrict__ Wc,
    const float* __restrict__ bc, __half* __restrict__ qout,
    __half* __restrict__ kout, __half* __restrict__ vout) {
    __shared__ __align__(16) __half XT[64 * XST];
    __shared__ __align__(16) __half WT[128 * WST];
    const int tid = threadIdx.x, lane = tid & 31, w = tid >> 5;
    const int wtile = blockIdx.x, n0 = blockIdx.y * 128, b = blockIdx.z;
    const float* Xb = X + (size_t)b * CIN * NPIX;
    const __half* Wrow = Wc + (size_t)wtile * 128 * CIN;

    const int wa = (w >> 2) * 64, wb = (w & 3) * 32;
    const uint32_t XTb = smem_u32(XT), WTb = smem_u32(WT);
    float d[4][4][4] = {};

    for (int ck = 0; ck < 4; ck++) {
        const int c0 = ck * 64;
#pragma unroll
        for (int it = 0; it < 8; it++) {
            int idx = it * 256 + tid;
            int cc = idx >> 5, ng = idx & 31;
            float4 x4 = *(const float4*)&Xb[(size_t)(c0 + cc) * NPIX + n0 + ng * 4];
            uint2 u;
            u.x = pk2(x4.x, x4.y);
            u.y = pk2(x4.z, x4.w);
            *(uint2*)&XT[cc * XST + ng * 4] = u;
        }
#pragma unroll
        for (int it = 0; it < 4; it++) {
            int idx = it * 256 + tid;
            int r = idx >> 3, g = idx & 7;
            *(uint4*)&WT[r * WST + g * 8] = *(const uint4*)&Wrow[(size_t)r * CIN + c0 + g * 8];
        }
        __syncthreads();

        if (wtile == 0) {
#pragma unroll
            for (int kk = 0; kk < 4; kk++) {
                const int kofs = kk * 16;
                uint32_t a[4][4], bb[4][2];
#pragma unroll
                for (int i = 0; i < 4; i++) {
                    int rc = kofs + (lane & 7) + (lane >> 4) * 8;
                    int cn = wa + i * 16 + ((lane >> 3) & 1) * 8;
                    ldsm_x4_t(a[i], XTb + (rc * XST + cn) * 2);
                }
#pragma unroll
                for (int j = 0; j < 4; j++) {
                    int l = lane & 15;
                    int row = wb + j * 8 + (l & 7);
                    int col = kofs + (l >> 3) * 8;
                    ldsm_x2(bb[j], WTb + (row * WST + col) * 2);
                }
#pragma unroll
                for (int i = 0; i < 4; i++)
#pragma unroll
                    for (int j = 0; j < 4; j++) mma16816(d[i][j], a[i], bb[j]);
            }
        } else {
#pragma unroll
            for (int kk = 0; kk < 4; kk++) {
                const int kofs = kk * 16;
                uint32_t a[4][4], bb[4][2];
#pragma unroll
                for (int i = 0; i < 4; i++) {
                    int row = wa + i * 16 + (lane & 7) + ((lane >> 3) & 1) * 8;
                    int col = kofs + (lane >> 4) * 8;
                    ldsm_x4(a[i], WTb + (row * WST + col) * 2);
                }
#pragma unroll
                for (int j = 0; j < 4; j++) {
                    int l = lane & 15;
                    int rc = kofs + l;
                    int cn = wb + j * 8;
                    ldsm_x2_t(bb[j], XTb + (rc * XST + cn) * 2);
                }
#pragma unroll
                for (int i = 0; i < 4; i++)
#pragma unroll
                    for (int j = 0; j < 4; j++) mma16816(d[i][j], a[i], bb[j]);
            }
        }
        __syncthreads();
    }

    if (wtile == 0) {
#pragma unroll
        for (int j = 0; j < 4; j++) {
            int o = wb + j * 8 + (lane & 3) * 2;
            float b0 = bc[o], b1 = bc[o + 1];
            __half* dst = o < 64 ? qout : kout;
            int oo = o < 64 ? o : o - 64;
#pragma unroll
            for (int i = 0; i < 4; i++) {
                int n = n0 + wa + i * 16 + (lane >> 2);
                float* dd = d[i][j];
                *(unsigned*)&dst[((size_t)b * NPIX + n) * CQK + oo] = pk2(dd[0] + b0, dd[1] + b1);
                *(unsigned*)&dst[((size_t)b * NPIX + n + 8) * CQK + oo] = pk2(dd[2] + b0, dd[3] + b1);
            }
        }
    } else {
#pragma unroll
        for (int i = 0; i < 4; i++) {
            int c = (wtile - 1) * 128 + wa + i * 16 + (lane >> 2);
            float b0 = bc[128 + c], b1 = bc[128 + c + 8];
#pragma unroll
            for (int j = 0; j < 4; j++) {
                int n = n0 + wb + j * 8 + (lane & 3) * 2;
                float* dd = d[i][j];
                *(unsigned*)&vout[((size_t)b * CIN + c) * NPIX + n] = pk2(dd[0] + b0, dd[1] + b0);
                *(unsigned*)&vout[((size_t)b * CIN + c + 8) * NPIX + n] = pk2(dd[2] + b1, dd[3] + b1);
            }
        }
    }
}

// ------------- fused attention: energy + AV, E never hits DRAM -------------
// CTA = (m-tile 64, batch). Output tile 256c x 64m fp32. 2 CTAs/SM.
// Loop n in 64-chunks: cp.async q[64n][64o], v[256c][64n] (double buffered);
// E[64m][64n] = elu(k.q^T) via HMMA -> fp16 smem; acc += v.E^T via HMMA.
#define FST 72
#define K_OFF 0
#define E_OFF (64 * FST)
#define Q_OFF (2 * 64 * FST)
#define QBUF  (64 * FST)
#define V_OFF (Q_OFF + 2 * QBUF)
#define VBUF  (256 * FST)
#define TOT_H (V_OFF + 2 * VBUF)  // 55296 halves = 110592 B

__global__ __launch_bounds__(256, 2) void fused_attn(
    const __half* __restrict__ qg, const __half* __restrict__ kg,
    const __half* __restrict__ vg, const float* __restrict__ bgb,
    float* __restrict__ out) {
    extern __shared__ __half sm[];
    const int tid = threadIdx.x, lane = tid & 31, w = tid >> 5;
    const int m0 = blockIdx.x * 64, b = blockIdx.y;
    const uint32_t smb = smem_u32(sm);

    // k tile [64 m][64 o], resident for the whole CTA
    const uint4* kg4 = (const uint4*)(kg + ((size_t)b * NPIX + m0) * CQK);
#pragma unroll
    for (int it = 0; it < 2; it++) {
        int idx = tid + 256 * it;
        int r = idx >> 3, s = idx & 7;
        *(uint4*)&sm[K_OFF + r * FST + s * 8] = kg4[idx];
    }

    const __half* qgb = qg + (size_t)b * NPIX * CQK;
    const __half* vgb = vg + (size_t)b * CIN * NPIX;

    auto prefetch = [&](int ch) {
        const int p = ch & 1;
        const int n0 = ch * 64;
        const uint32_t qdst = smb + (Q_OFF + p * QBUF) * 2;
        {
            int r = tid >> 3, s = tid & 7;  // 512 uint4, 256 thr -> 2 rows each
            CP_ASYNC16(qdst + (r * FST + s * 8) * 2, qgb + (size_t)(n0 + r) * CQK + s * 8);
            CP_ASYNC16(qdst + ((r + 32) * FST + s * 8) * 2, qgb + (size_t)(n0 + r + 32) * CQK + s * 8);
        }
        const uint32_t vdst = smb + (V_OFF + p * VBUF) * 2;
#pragma unroll
        for (int it = 0; it < 8; it++) {
            int idx = tid + 256 * it;
            int r = idx >> 3, s = idx & 7;
            CP_ASYNC16(vdst + (r * FST + s * 8) * 2, vgb + (size_t)r * NPIX + n0 + s * 8);
        }
        CP_COMMIT();
    };

    prefetch(0);
    prefetch(1);

    const int wme = (w & 1) * 32, wne = (w >> 1) * 16;   // energy warp: 32m x 16n
    const int wc  = (w & 3) * 64, wmm = (w >> 2) * 32;   // AV warp: 64c x 32m
    const uint32_t ksb = smb + K_OFF * 2;
    const uint32_t esb = smb + E_OFF * 2;

    float acc[4][4][4] = {};

    for (int ch = 0; ch < NCH; ch++) {
        const int p = ch & 1;
        const uint32_t qsb = smb + (Q_OFF + p * QBUF) * 2;
        const uint32_t vsb = smb + (V_OFF + p * VBUF) * 2;

        if (ch == NCH - 1) CP_WAIT(0); else CP_WAIT(1);
        __syncthreads();

        // ---- energy stage: E[64m][64n] = elu(k . q^T)
        float de[2][2][4] = {};
#pragma unroll
        for (int kk = 0; kk < 4; kk++) {
            const int ko = kk * 16;
            uint32_t a[2][4], bb[2][2];
#pragma unroll
            for (int i = 0; i < 2; i++) {
                int row = wme + i * 16 + (lane & 7) + ((lane >> 3) & 1) * 8;
                int col = ko + (lane >> 4) * 8;
                ldsm_x4(a[i], ksb + (row * FST + col) * 2);
            }
#pragma unroll
            for (int j = 0; j < 2; j++) {
                int l = lane & 15;
                int row = wne + j * 8 + (l & 7);
                int col = ko + (l >> 3) * 8;
                ldsm_x2(bb[j], qsb + (row * FST + col) * 2);
            }
#pragma unroll
            for (int i = 0; i < 2; i++)
#pragma unroll
                for (int j = 0; j < 2; j++) mma16816(de[i][j], a[i], bb[j]);
        }
#pragma unroll
        for (int i = 0; i < 2; i++) {
            int m = wme + i * 16 + (lane >> 2);
#pragma unroll
            for (int j = 0; j < 2; j++) {
                int n = wne + j * 8 + (lane & 3) * 2;
                float* dd = de[i][j];
                *(unsigned*)&sm[E_OFF + m * FST + n]       = pk2(eluf(dd[0]), eluf(dd[1]));
                *(unsigned*)&sm[E_OFF + (m + 8) * FST + n] = pk2(eluf(dd[2]), eluf(dd[3]));
            }
        }
        __syncthreads();

        // ---- AV stage: acc[c][m] += v . E^T
#pragma unroll
        for (int kk = 0; kk < 4; kk++) {
            const int ko = kk * 16;
            uint32_t a[4][4], bb[4][2];
#pragma unroll
            for (int i = 0; i < 4; i++) {
                int row = wc + i * 16 + (lane & 7) + ((lane >> 3) & 1) * 8;
                int col = ko + (lane >> 4) * 8;
                ldsm_x4(a[i], vsb + (row * FST + col) * 2);
            }
#pragma unroll
            for (int j = 0; j < 4; j++) {
                int l = lane & 15;
                int row = wmm + j * 8 + (l & 7);
                int col = ko + (l >> 3) * 8;
                ldsm_x2(bb[j], esb + (row * FST + col) * 2);
            }
#pragma unroll
            for (int i = 0; i < 4; i++)
#pragma unroll
                for (int j = 0; j < 4; j++) mma16816(acc[i][j], a[i], bb[j]);
        }
        __syncthreads();

        if (ch + 2 < NCH) prefetch(ch + 2);
    }

    // ---- epilogue: /N + bias
    const float scale = 1.0f / (float)NPIX;
#pragma unroll
    for (int i = 0; i < 4; i++) {
        int c = wc + i * 16 + (lane >> 2);
        float b0 = bgb[c], b1 = bgb[c + 8];
#pragma unroll
        for (int j = 0; j < 4; j++) {
            int m = m0 + wmm + j * 8 + (lane & 3) * 2;
            float* dd = acc[i][j];
            *(float2*)&out[((size_t)b * CIN + c) * NPIX + m] =
                make_float2(dd[0] * scale + b0, dd[1] * scale + b0);
            *(float2*)&out[((size_t)b * CIN + c + 8) * NPIX + m] =
                make_float2(dd[2] * scale + b1, dd[3] * scale + b1);
        }
    }
}

// ------------------------------- launch -------------------------------------
extern "C" void kernel_launch(void* const* d_in, const int* in_sizes, int n_in,
                              void* d_out, int out_size) {
    const float* x  = (const float*)d_in[0];
    const float* wq = (const float*)d_in[1];
    const float* bq = (const float*)d_in[2];
    const float* wk = (const float*)d_in[3];
    const float* bk = (const float*)d_in[4];
    const float* wv = (const float*)d_in[5];
    const float* bv = (const float*)d_in[6];
    const float* wg = (const float*)d_in[7];
    const float* bg = (const float*)d_in[8];
    float* out = (float*)d_out;

    float *w2p, *bcp;
    __half *wcp, *qp, *kp, *vp;
    cudaGetSymbolAddress((void**)&w2p, g_w2);
    cudaGetSymbolAddress((void**)&wcp, g_wc);
    cudaGetSymbolAddress((void**)&bcp, g_bc);
    cudaGetSymbolAddress((void**)&qp, g_q);
    cudaGetSymbolAddress((void**)&kp, g_k);
    cudaGetSymbolAddress((void**)&vp, g_v);

    const int F_SMEM = TOT_H * (int)sizeof(__half);  // 110592
    cudaFuncSetAttribute(fused_attn, cudaFuncAttributeMaxDynamicSharedMemorySize, F_SMEM);

    fold_w<<<CIN, CIN>>>(wg, wv, w2p);
    pack_weights<<<384, CIN>>>(wq, wk, w2p, bq, bk, wg, bv, wcp, bcp);

    proj_qkv<<<dim3(3, NPIX / 128, BATCH), 256>>>(x, wcp, bcp, qp, kp, vp);

    fused_attn<<<dim3(NPIX / 64, BATCH), 256, F_SMEM>>>(qp, kp, vp, bg, out);
}

// round 9
// speedup vs baseline: 1.1122x; 1.1122x over previous
#include <cuda_runtime.h>
#include <cuda_fp16.h>
#include <cstdint>

#define NPIX 4096
#define CIN  256
#define CQK  64
#define BATCH 4
#define NCH  (NPIX / 64)

// ------------------------- device scratch ----------------------------------
__device__ float  g_w2[CIN * CIN];
__device__ __half g_wc[384 * CIN];
__device__ float  g_bc[384];
__device__ __half g_q[(size_t)BATCH * NPIX * CQK];   // [b][n][o]
__device__ __half g_k[(size_t)BATCH * NPIX * CQK];   // [b][m][o]
__device__ __half g_v[(size_t)BATCH * CIN * NPIX];   // [b][c][n]

// ------------------------- helpers -----------------------------------------
__device__ __forceinline__ uint32_t smem_u32(const void* p) {
    uint32_t a;
    asm("{ .reg .u64 t; cvta.to.shared.u64 t, %1; cvt.u32.u64 %0, t; }" : "=r"(a) : "l"(p));
    return a;
}
__device__ __forceinline__ void ldsm_x4(uint32_t a[4], uint32_t addr) {
    asm volatile("ldmatrix.sync.aligned.m8n8.x4.shared.b16 {%0,%1,%2,%3}, [%4];"
                 : "=r"(a[0]), "=r"(a[1]), "=r"(a[2]), "=r"(a[3]) : "r"(addr));
}
__device__ __forceinline__ void ldsm_x2(uint32_t a[2], uint32_t addr) {
    asm volatile("ldmatrix.sync.aligned.m8n8.x2.shared.b16 {%0,%1}, [%2];"
                 : "=r"(a[0]), "=r"(a[1]) : "r"(addr));
}
__device__ __forceinline__ void ldsm_x4_t(uint32_t a[4], uint32_t addr) {
    asm volatile("ldmatrix.sync.aligned.m8n8.x4.trans.shared.b16 {%0,%1,%2,%3}, [%4];"
                 : "=r"(a[0]), "=r"(a[1]), "=r"(a[2]), "=r"(a[3]) : "r"(addr));
}
__device__ __forceinline__ void ldsm_x2_t(uint32_t a[2], uint32_t addr) {
    asm volatile("ldmatrix.sync.aligned.m8n8.x2.trans.shared.b16 {%0,%1}, [%2];"
                 : "=r"(a[0]), "=r"(a[1]) : "r"(addr));
}
__device__ __forceinline__ void mma16816(float d[4], const uint32_t a[4], const uint32_t* b) {
    asm volatile(
        "mma.sync.aligned.m16n8k16.row.col.f32.f16.f16.f32 "
        "{%0,%1,%2,%3}, {%4,%5,%6,%7}, {%8,%9}, {%0,%1,%2,%3};"
        : "+f"(d[0]), "+f"(d[1]), "+f"(d[2]), "+f"(d[3])
        : "r"(a[0]), "r"(a[1]), "r"(a[2]), "r"(a[3]), "r"(b[0]), "r"(b[1]));
}
#define CP_ASYNC16(dst, src) \
    asm volatile("cp.async.cg.shared.global [%0], [%1], 16;" :: "r"(dst), "l"(src))
#define CP_COMMIT() asm volatile("cp.async.commit_group;" ::: "memory")
#define CP_WAIT(n)  asm volatile("cp.async.wait_group %0;" :: "n"(n) : "memory")

__device__ __forceinline__ float eluf(float x) { return x > 0.f ? x : (__expf(x) - 1.f); }
__device__ __forceinline__ unsigned pk2(float a, float b) {
    __half2 h = __floats2half2_rn(a, b);
    return *(unsigned*)&h;
}

// ------------------------- weight folding / packing ------------------------
__global__ void fold_w(const float* __restrict__ wg, const float* __restrict__ wv,
                       float* __restrict__ w2) {
    int o = blockIdx.x, j = threadIdx.x;
    float s = 0.f;
    for (int c = 0; c < CIN; c++) s += wg[o * CIN + c] * wv[c * CIN + j];
    w2[o * CIN + j] = s;
}
__global__ void pack_weights(const float* __restrict__ wq, const float* __restrict__ wk,
                             const float* __restrict__ w2, const float* __restrict__ bq,
                             const float* __restrict__ bk, const float* __restrict__ wg,
                             const float* __restrict__ bv, __half* __restrict__ Wc,
                             float* __restrict__ bc) {
    int r = blockIdx.x, c = threadIdx.x;
    const float* src = r < 64 ? wq + r * CIN : (r < 128 ? wk + (r - 64) * CIN : w2 + (r - 128) * CIN);
    Wc[r * CIN + c] = __float2half(src[c]);
    if (c == 0) {
        if (r < 64) bc[r] = bq[r];
        else if (r < 128) bc[r] = bk[r - 64];
        else {
            float s = 0.f;
            int o = r - 128;
            for (int cc = 0; cc < CIN; cc++) s += wg[o * CIN + cc] * bv[cc];
            bc[r] = s;
        }
    }
}

// ----------------- fused QKV projection (HMMA, fp16) -----------------------
#define XST 136
#define WST 72

__global__ __launch_bounds__(256) void proj_qkv(
    const float* __restrict__ X, const __half* __restrict__ Wc,
    const float* __restrict__ bc, __half* __restrict__ qout,
    __half* __restrict__ kout, __half* __restrict__ vout) {
    __shared__ __align__(16) __half XT[64 * XST];
    __shared__ __align__(16) __half WT[128 * WST];
    const int tid = threadIdx.x, lane = tid & 31, w = tid >> 5;
    const int wtile = blockIdx.x, n0 = blockIdx.y * 128, b = blockIdx.z;
    const float* Xb = X + (size_t)b * CIN * NPIX;
    const __half* Wrow = Wc + (size_t)wtile * 128 * CIN;

    const int wa = (w >> 2) * 64, wb = (w & 3) * 32;
    const uint32_t XTb = smem_u32(XT), WTb = smem_u32(WT);
    float d[4][4][4] = {};

    for (int ck = 0; ck < 4; ck++) {
        const int c0 = ck * 64;
#pragma unroll
        for (int it = 0; it < 8; it++) {
            int idx = it * 256 + tid;
            int cc = idx >> 5, ng = idx & 31;
            float4 x4 = *(const float4*)&Xb[(size_t)(c0 + cc) * NPIX + n0 + ng * 4];
            uint2 u;
            u.x = pk2(x4.x, x4.y);
            u.y = pk2(x4.z, x4.w);
            *(uint2*)&XT[cc * XST + ng * 4] = u;
        }
#pragma unroll
        for (int it = 0; it < 4; it++) {
            int idx = it * 256 + tid;
            int r = idx >> 3, g = idx & 7;
            *(uint4*)&WT[r * WST + g * 8] = *(const uint4*)&Wrow[(size_t)r * CIN + c0 + g * 8];
        }
        __syncthreads();

        if (wtile == 0) {
#pragma unroll
            for (int kk = 0; kk < 4; kk++) {
                const int kofs = kk * 16;
                uint32_t a[4][4], bb[4][2];
#pragma unroll
                for (int i = 0; i < 4; i++) {
                    int rc = kofs + (lane & 7) + (lane >> 4) * 8;
                    int cn = wa + i * 16 + ((lane >> 3) & 1) * 8;
                    ldsm_x4_t(a[i], XTb + (rc * XST + cn) * 2);
                }
#pragma unroll
                for (int j = 0; j < 4; j++) {
                    int l = lane & 15;
                    int row = wb + j * 8 + (l & 7);
                    int col = kofs + (l >> 3) * 8;
                    ldsm_x2(bb[j], WTb + (row * WST + col) * 2);
                }
#pragma unroll
                for (int i = 0; i < 4; i++)
#pragma unroll
                    for (int j = 0; j < 4; j++) mma16816(d[i][j], a[i], bb[j]);
            }
        } else {
#pragma unroll
            for (int kk = 0; kk < 4; kk++) {
                const int kofs = kk * 16;
                uint32_t a[4][4], bb[4][2];
#pragma unroll
                for (int i = 0; i < 4; i++) {
                    int row = wa + i * 16 + (lane & 7) + ((lane >> 3) & 1) * 8;
                    int col = kofs + (lane >> 4) * 8;
                    ldsm_x4(a[i], WTb + (row * WST + col) * 2);
                }
#pragma unroll
                for (int j = 0; j < 4; j++) {
                    int l = lane & 15;
                    int rc = kofs + l;
                    int cn = wb + j * 8;
                    ldsm_x2_t(bb[j], XTb + (rc * XST + cn) * 2);
                }
#pragma unroll
                for (int i = 0; i < 4; i++)
#pragma unroll
                    for (int j = 0; j < 4; j++) mma16816(d[i][j], a[i], bb[j]);
            }
        }
        __syncthreads();
    }

    if (wtile == 0) {
#pragma unroll
        for (int j = 0; j < 4; j++) {
            int o = wb + j * 8 + (lane & 3) * 2;
            float b0 = bc[o], b1 = bc[o + 1];
            __half* dst = o < 64 ? qout : kout;
            int oo = o < 64 ? o : o - 64;
#pragma unroll
            for (int i = 0; i < 4; i++) {
                int n = n0 + wa + i * 16 + (lane >> 2);
                float* dd = d[i][j];
                *(unsigned*)&dst[((size_t)b * NPIX + n) * CQK + oo] = pk2(dd[0] + b0, dd[1] + b1);
                *(unsigned*)&dst[((size_t)b * NPIX + n + 8) * CQK + oo] = pk2(dd[2] + b0, dd[3] + b1);
            }
        }
    } else {
#pragma unroll
        for (int i = 0; i < 4; i++) {
            int c = (wtile - 1) * 128 + wa + i * 16 + (lane >> 2);
            float b0 = bc[128 + c], b1 = bc[128 + c + 8];
#pragma unroll
            for (int j = 0; j < 4; j++) {
                int n = n0 + wb + j * 8 + (lane & 3) * 2;
                float* dd = d[i][j];
                *(unsigned*)&vout[((size_t)b * CIN + c) * NPIX + n] = pk2(dd[0] + b0, dd[1] + b0);
                *(unsigned*)&vout[((size_t)b * CIN + c + 8) * NPIX + n] = pk2(dd[2] + b1, dd[3] + b1);
            }
        }
    }
}

// ------------- fused attention: pipelined energy + AV ----------------------
// CTA = (m-tile 128, batch), 256 thr, 1 CTA/SM.
// Per chunk (single __syncthreads): AV(ch) on E[ch&1]; energy(ch+1) -> E[(ch+1)&1].
// q,v triple-buffered via cp.async; v swizzled (stride 64, no pad).
#define FST 72   // k, q stride (halves)
#define EST 72   // E stride (halves) — tile is 128 x 64, stride >= 64 + pad
#define K_OFF 0                           // 128*72 = 9216
#define E_OFF(p) (9216 + (p) * 9216)      // 2 x 128*72
#define Q_OFF(i) (27648 + (i) * 4608)     // 3 x 64*72
#define V_OFF(i) (41472 + (i) * 16384)    // 3 x 256*64 (swizzled)
#define TOT_H 90624                       // halves = 181248 B

__global__ __launch_bounds__(256, 1) void fused_attn(
    const __half* __restrict__ qg, const __half* __restrict__ kg,
    const __half* __restrict__ vg, const float* __restrict__ bgb,
    float* __restrict__ out) {
    extern __shared__ __half sm[];
    const int tid = threadIdx.x, lane = tid & 31, w = tid >> 5;
    const int m0 = blockIdx.x * 128, b = blockIdx.y;
    const uint32_t smb = smem_u32(sm);

    const __half* qgb = qg + (size_t)b * NPIX * CQK;
    const __half* vgb = vg + (size_t)b * CIN * NPIX;

    // ---- prologue loads: k tile + q(0) (direct), then async groups 0,1
    {
        const uint4* kg4 = (const uint4*)(kg + ((size_t)b * NPIX + m0) * CQK);
#pragma unroll
        for (int it = 0; it < 4; it++) {
            int idx = tid + 256 * it;  // 1024 = 128 rows x 8
            int r = idx >> 3, s = idx & 7;
            *(uint4*)&sm[K_OFF + r * FST + s * 8] = kg4[idx];
        }
        const uint4* qg4 = (const uint4*)qgb;
#pragma unroll
        for (int it = 0; it < 2; it++) {
            int idx = tid + 256 * it;  // 512 = 64 rows x 8
            int r = idx >> 3, s = idx & 7;
            *(uint4*)&sm[Q_OFF(0) + r * FST + s * 8] = qg4[idx];
        }
    }

    auto prefetch = [&](int i) {  // group i: v(i) -> V(i%3), q(i+1) -> Q((i+1)%3)
        const int n0 = i * 64;
        const uint32_t vdst = smb + V_OFF(i % 3) * 2;
#pragma unroll
        for (int it = 0; it < 8; it++) {
            int idx = tid + 256 * it;  // 2048 = 256 rows x 8
            int r = idx >> 3, s = idx & 7;
            CP_ASYNC16(vdst + (r * 64 + ((s ^ (r & 7)) * 8)) * 2,
                       vgb + (size_t)r * NPIX + n0 + s * 8);
        }
        if (i + 1 < NCH) {
            const uint32_t qdst = smb + Q_OFF((i + 1) % 3) * 2;
            int r = tid >> 3, s = tid & 7;
            CP_ASYNC16(qdst + (r * FST + s * 8) * 2,
                       qgb + (size_t)((i + 1) * 64 + r) * CQK + s * 8);
            CP_ASYNC16(qdst + ((r + 32) * FST + s * 8) * 2,
                       qgb + (size_t)((i + 1) * 64 + r + 32) * CQK + s * 8);
        }
        CP_COMMIT();
    };

    prefetch(0);
    prefetch(1);
    __syncthreads();  // k, q(0) visible

    const uint32_t ksb = smb + K_OFF * 2;
    const int wme = w * 16;                              // energy warp: 16m x 64n
    const int wc = (w >> 1) * 64, wm = (w & 1) * 64;     // AV warp: 64c x 64m

    // ---- energy for a chunk: E[en & 1] = elu(k . q(en)^T), warp rows wme..+16
    auto energy = [&](int en) {
        const uint32_t qsb = smb + Q_OFF(en % 3) * 2;
        const uint32_t edst = smb + E_OFF(en & 1) * 2;
        float de[8][4] = {};
#pragma unroll
        for (int kk = 0; kk < 4; kk++) {
            const int ko = kk * 16;
            uint32_t a[4];
            {
                int row = wme + (lane & 7) + ((lane >> 3) & 1) * 8;
                int col = ko + (lane >> 4) * 8;
                ldsm_x4(a, ksb + (row * FST + col) * 2);
            }
#pragma unroll
            for (int g = 0; g < 4; g++) {
                uint32_t b4[4];
                int row = g * 16 + (lane & 7) + (lane >> 4) * 8;
                int col = ko + ((lane >> 3) & 1) * 8;
                ldsm_x4(b4, qsb + (row * FST + col) * 2);
                mma16816(de[2 * g], a, b4);
                mma16816(de[2 * g + 1], a, b4 + 2);
            }
        }
        // elu -> fp16 -> E buffer
        const int m = wme + (lane >> 2);
        const int n = (lane & 3) * 2;
#pragma unroll
        for (int j = 0; j < 8; j++) {
            float* dd = de[j];
            asm volatile("st.shared.u32 [%0], %1;" ::
                         "r"(edst + (m * EST + n + j * 8) * 2), "r"(pk2(eluf(dd[0]), eluf(dd[1]))));
            asm volatile("st.shared.u32 [%0], %1;" ::
                         "r"(edst + ((m + 8) * EST + n + j * 8) * 2), "r"(pk2(eluf(dd[2]), eluf(dd[3]))));
        }
    };

    // prologue energy for chunk 0
    energy(0);

    float acc[4][8][4] = {};

    for (int ch = 0; ch < NCH; ch++) {
        if (ch >= NCH - 1) CP_WAIT(0); else CP_WAIT(1);
        __syncthreads();

        if (ch + 2 < NCH) prefetch(ch + 2);

        // ---- AV(ch): acc[c][m] += v . E^T
        {
            const uint32_t vsb = smb + V_OFF(ch % 3) * 2;
            const uint32_t esb = smb + E_OFF(ch & 1) * 2;
#pragma unroll
            for (int kk = 0; kk < 4; kk++) {
                const int ko = kk * 16;
                uint32_t a[4][4];
#pragma unroll
                for (int i = 0; i < 4; i++) {
                    int row = wc + i * 16 + (lane & 7) + ((lane >> 3) & 1) * 8;
                    int chunk = (ko >> 3) + (lane >> 4);
                    ldsm_x4(a[i], vsb + (row * 64 + ((chunk ^ (row & 7)) * 8)) * 2);
                }
#pragma unroll
                for (int g = 0; g < 4; g++) {
                    uint32_t b4[4];
                    int row = wm + g * 16 + (lane & 7) + (lane >> 4) * 8;
                    int col = ko + ((lane >> 3) & 1) * 8;
                    ldsm_x4(b4, esb + (row * EST + col) * 2);
#pragma unroll
                    for (int i = 0; i < 4; i++) {
                        mma16816(acc[i][2 * g], a[i], b4);
                        mma16816(acc[i][2 * g + 1], a[i], b4 + 2);
                    }
                }
            }
        }

        // ---- energy(ch+1) -> E[(ch+1)&1]
        if (ch + 1 < NCH) energy(ch + 1);
    }

    // ---- epilogue: /N + bias
    const float scale = 1.0f / (float)NPIX;
#pragma unroll
    for (int i = 0; i < 4; i++) {
        int c = wc + i * 16 + (lane >> 2);
        float b0 = bgb[c], b1 = bgb[c + 8];
#pragma unroll
        for (int j = 0; j < 8; j++) {
            int m = m0 + wm + j * 8 + (lane & 3) * 2;
            float* dd = acc[i][j];
            *(float2*)&out[((size_t)b * CIN + c) * NPIX + m] =
                make_float2(dd[0] * scale + b0, dd[1] * scale + b0);
            *(float2*)&out[((size_t)b * CIN + c + 8) * NPIX + m] =
                make_float2(dd[2] * scale + b1, dd[3] * scale + b1);
        }
    }
}

// ------------------------------- launch -------------------------------------
extern "C" void kernel_launch(void* const* d_in, const int* in_sizes, int n_in,
                              void* d_out, int out_size) {
    const float* x  = (const float*)d_in[0];
    const float* wq = (const float*)d_in[1];
    const float* bq = (const float*)d_in[2];
    const float* wk = (const float*)d_in[3];
    const float* bk = (const float*)d_in[4];
    const float* wv = (const float*)d_in[5];
    const float* bv = (const float*)d_in[6];
    const float* wg = (const float*)d_in[7];
    const float* bg = (const float*)d_in[8];
    float* out = (float*)d_out;

    float *w2p, *bcp;
    __half *wcp, *qp, *kp, *vp;
    cudaGetSymbolAddress((void**)&w2p, g_w2);
    cudaGetSymbolAddress((void**)&wcp, g_wc);
    cudaGetSymbolAddress((void**)&bcp, g_bc);
    cudaGetSymbolAddress((void**)&qp, g_q);
    cudaGetSymbolAddress((void**)&kp, g_k);
    cudaGetSymbolAddress((void**)&vp, g_v);

    const int F_SMEM = TOT_H * (int)sizeof(__half);  // 181248
    cudaFuncSetAttribute(fused_attn, cudaFuncAttributeMaxDynamicSharedMemorySize, F_SMEM);

    fold_w<<<CIN, CIN>>>(wg, wv, w2p);
    pack_weights<<<384, CIN>>>(wq, wk, w2p, bq, bk, wg, bv, wcp, bcp);

    proj_qkv<<<dim3(3, NPIX / 128, BATCH), 256>>>(x, wcp, bcp, qp, kp, vp);

    fused_attn<<<dim3(NPIX / 128, BATCH), 256, F_SMEM>>>(qp, kp, vp, bg, out);
}

// round 10
// speedup vs baseline: 1.2445x; 1.1189x over previous
#include <cuda_runtime.h>
#include <cuda_fp16.h>
#include <cstdint>

#define NPIX 4096
#define CIN  256
#define CQK  64
#define BATCH 4
#define NCH  (NPIX / 64)

// ------------------------- device scratch ----------------------------------
__device__ float  g_w2[CIN * CIN];
__device__ __half g_wc[384 * CIN];
__device__ float  g_bc[384];
__device__ __half g_q[(size_t)BATCH * NPIX * CQK];   // [b][n][o]
__device__ __half g_k[(size_t)BATCH * NPIX * CQK];   // [b][m][o]
__device__ __half g_v[(size_t)BATCH * CIN * NPIX];   // [b][c][n]

// ------------------------- helpers -----------------------------------------
__device__ __forceinline__ uint32_t smem_u32(const void* p) {
    uint32_t a;
    asm("{ .reg .u64 t; cvta.to.shared.u64 t, %1; cvt.u32.u64 %0, t; }" : "=r"(a) : "l"(p));
    return a;
}
__device__ __forceinline__ void ldsm_x4(uint32_t a[4], uint32_t addr) {
    asm volatile("ldmatrix.sync.aligned.m8n8.x4.shared.b16 {%0,%1,%2,%3}, [%4];"
                 : "=r"(a[0]), "=r"(a[1]), "=r"(a[2]), "=r"(a[3]) : "r"(addr));
}
__device__ __forceinline__ void ldsm_x2(uint32_t a[2], uint32_t addr) {
    asm volatile("ldmatrix.sync.aligned.m8n8.x2.shared.b16 {%0,%1}, [%2];"
                 : "=r"(a[0]), "=r"(a[1]) : "r"(addr));
}
__device__ __forceinline__ void ldsm_x4_t(uint32_t a[4], uint32_t addr) {
    asm volatile("ldmatrix.sync.aligned.m8n8.x4.trans.shared.b16 {%0,%1,%2,%3}, [%4];"
                 : "=r"(a[0]), "=r"(a[1]), "=r"(a[2]), "=r"(a[3]) : "r"(addr));
}
__device__ __forceinline__ void ldsm_x2_t(uint32_t a[2], uint32_t addr) {
    asm volatile("ldmatrix.sync.aligned.m8n8.x2.trans.shared.b16 {%0,%1}, [%2];"
                 : "=r"(a[0]), "=r"(a[1]) : "r"(addr));
}
__device__ __forceinline__ void mma16816(float d[4], const uint32_t a[4], const uint32_t* b) {
    asm volatile(
        "mma.sync.aligned.m16n8k16.row.col.f32.f16.f16.f32 "
        "{%0,%1,%2,%3}, {%4,%5,%6,%7}, {%8,%9}, {%0,%1,%2,%3};"
        : "+f"(d[0]), "+f"(d[1]), "+f"(d[2]), "+f"(d[3])
        : "r"(a[0]), "r"(a[1]), "r"(a[2]), "r"(a[3]), "r"(b[0]), "r"(b[1]));
}
#define CP_ASYNC16(dst, src) \
    asm volatile("cp.async.cg.shared.global [%0], [%1], 16;" :: "r"(dst), "l"(src))
#define CP_COMMIT() asm volatile("cp.async.commit_group;" ::: "memory")
#define CP_WAIT(n)  asm volatile("cp.async.wait_group %0;" :: "n"(n) : "memory")

__device__ __forceinline__ float eluf(float x) { return x > 0.f ? x : (__expf(x) - 1.f); }
__device__ __forceinline__ unsigned pk2(float a, float b) {
    __half2 h = __floats2half2_rn(a, b);
    return *(unsigned*)&h;
}
// elu on a packed fp16x2 pair: x>0 ? x : exp(x)-1, one MUFU per 2 values
__device__ __forceinline__ unsigned elu2(float x0, float x1) {
    __half2 h = __floats2half2_rn(x0, x1);
    __half2 hl = __hmul2(h, __float2half2_rn(1.44269504f));
    unsigned eu;
    asm("ex2.approx.f16x2 %0, %1;" : "=r"(eu) : "r"(*(unsigned*)&hl));
    __half2 em1 = __hsub2(*(__half2*)&eu, __float2half2_rn(1.0f));
    __half2 mask = __hgt2(h, __float2half2_rn(0.0f));       // 1.0 where x>0
    __half2 r = __hfma2(mask, __hsub2(h, em1), em1);        // em1 + mask*(h-em1)
    return *(unsigned*)&r;
}

// ------------------------- weight folding / packing ------------------------
__global__ void fold_w(const float* __restrict__ wg, const float* __restrict__ wv,
                       float* __restrict__ w2) {
    int o = blockIdx.x, j = threadIdx.x;
    float s = 0.f;
    for (int c = 0; c < CIN; c++) s += wg[o * CIN + c] * wv[c * CIN + j];
    w2[o * CIN + j] = s;
}
__global__ void pack_weights(const float* __restrict__ wq, const float* __restrict__ wk,
                             const float* __restrict__ w2, const float* __restrict__ bq,
                             const float* __restrict__ bk, const float* __restrict__ wg,
                             const float* __restrict__ bv, __half* __restrict__ Wc,
                             float* __restrict__ bc) {
    int r = blockIdx.x, c = threadIdx.x;
    const float* src = r < 64 ? wq + r * CIN : (r < 128 ? wk + (r - 64) * CIN : w2 + (r - 128) * CIN);
    Wc[r * CIN + c] = __float2half(src[c]);
    if (c == 0) {
        if (r < 64) bc[r] = bq[r];
        else if (r < 128) bc[r] = bk[r - 64];
        else {
            float s = 0.f;
            int o = r - 128;
            for (int cc = 0; cc < CIN; cc++) s += wg[o * CIN + cc] * bv[cc];
            bc[r] = s;
        }
    }
}

// ----------------- fused QKV projection (HMMA, fp16) -----------------------
#define XST 136
#define WST 72

__global__ __launch_bounds__(256) void proj_qkv(
    const float* __restrict__ X, const __half* __restrict__ Wc,
    const float* __restrict__ bc, __half* __restrict__ qout,
    __half* __restrict__ kout, __half* __restrict__ vout) {
    __shared__ __align__(16) __half XT[64 * XST];
    __shared__ __align__(16) __half WT[128 * WST];
    const int tid = threadIdx.x, lane = tid & 31, w = tid >> 5;
    const int wtile = blockIdx.x, n0 = blockIdx.y * 128, b = blockIdx.z;
    const float* Xb = X + (size_t)b * CIN * NPIX;
    const __half* Wrow = Wc + (size_t)wtile * 128 * CIN;

    const int wa = (w >> 2) * 64, wb = (w & 3) * 32;
    const uint32_t XTb = smem_u32(XT), WTb = smem_u32(WT);
    float d[4][4][4] = {};

    for (int ck = 0; ck < 4; ck++) {
        const int c0 = ck * 64;
#pragma unroll
        for (int it = 0; it < 8; it++) {
            int idx = it * 256 + tid;
            int cc = idx >> 5, ng = idx & 31;
            float4 x4 = *(const float4*)&Xb[(size_t)(c0 + cc) * NPIX + n0 + ng * 4];
            uint2 u;
            u.x = pk2(x4.x, x4.y);
            u.y = pk2(x4.z, x4.w);
            *(uint2*)&XT[cc * XST + ng * 4] = u;
        }
#pragma unroll
        for (int it = 0; it < 4; it++) {
            int idx = it * 256 + tid;
            int r = idx >> 3, g = idx & 7;
            *(uint4*)&WT[r * WST + g * 8] = *(const uint4*)&Wrow[(size_t)r * CIN + c0 + g * 8];
        }
        __syncthreads();

        if (wtile == 0) {
#pragma unroll
            for (int kk = 0; kk < 4; kk++) {
                const int kofs = kk * 16;
                uint32_t a[4][4], bb[4][2];
#pragma unroll
                for (int i = 0; i < 4; i++) {
                    int rc = kofs + (lane & 7) + (lane >> 4) * 8;
                    int cn = wa + i * 16 + ((lane >> 3) & 1) * 8;
                    ldsm_x4_t(a[i], XTb + (rc * XST + cn) * 2);
                }
#pragma unroll
                for (int j = 0; j < 4; j++) {
                    int l = lane & 15;
                    int row = wb + j * 8 + (l & 7);
                    int col = kofs + (l >> 3) * 8;
                    ldsm_x2(bb[j], WTb + (row * WST + col) * 2);
                }
#pragma unroll
                for (int i = 0; i < 4; i++)
#pragma unroll
                    for (int j = 0; j < 4; j++) mma16816(d[i][j], a[i], bb[j]);
            }
        } else {
#pragma unroll
            for (int kk = 0; kk < 4; kk++) {
                const int kofs = kk * 16;
                uint32_t a[4][4], bb[4][2];
#pragma unroll
                for (int i = 0; i < 4; i++) {
                    int row = wa + i * 16 + (lane & 7) + ((lane >> 3) & 1) * 8;
                    int col = kofs + (lane >> 4) * 8;
                    ldsm_x4(a[i], WTb + (row * WST + col) * 2);
                }
#pragma unroll
                for (int j = 0; j < 4; j++) {
                    int l = lane & 15;
                    int rc = kofs + l;
                    int cn = wb + j * 8;
                    ldsm_x2_t(bb[j], XTb + (rc * XST + cn) * 2);
                }
#pragma unroll
                for (int i = 0; i < 4; i++)
#pragma unroll
                    for (int j = 0; j < 4; j++) mma16816(d[i][j], a[i], bb[j]);
            }
        }
        __syncthreads();
    }

    if (wtile == 0) {
#pragma unroll
        for (int j = 0; j < 4; j++) {
            int o = wb + j * 8 + (lane & 3) * 2;
            float b0 = bc[o], b1 = bc[o + 1];
            __half* dst = o < 64 ? qout : kout;
            int oo = o < 64 ? o : o - 64;
#pragma unroll
            for (int i = 0; i < 4; i++) {
                int n = n0 + wa + i * 16 + (lane >> 2);
                float* dd = d[i][j];
                *(unsigned*)&dst[((size_t)b * NPIX + n) * CQK + oo] = pk2(dd[0] + b0, dd[1] + b1);
                *(unsigned*)&dst[((size_t)b * NPIX + n + 8) * CQK + oo] = pk2(dd[2] + b0, dd[3] + b1);
            }
        }
    } else {
#pragma unroll
        for (int i = 0; i < 4; i++) {
            int c = (wtile - 1) * 128 + wa + i * 16 + (lane >> 2);
            float b0 = bc[128 + c], b1 = bc[128 + c + 8];
#pragma unroll
            for (int j = 0; j < 4; j++) {
                int n = n0 + wb + j * 8 + (lane & 3) * 2;
                float* dd = d[i][j];
                *(unsigned*)&vout[((size_t)b * CIN + c) * NPIX + n] = pk2(dd[0] + b0, dd[1] + b0);
                *(unsigned*)&vout[((size_t)b * CIN + c + 8) * NPIX + n] = pk2(dd[2] + b1, dd[3] + b1);
            }
        }
    }
}

// ------------- fused attention: pipelined energy + AV, 512 threads ---------
// CTA = (m-tile 128, batch), 512 thr (16 warps, 4/SMSP), 1 CTA/SM.
// Per chunk (single __syncthreads): AV(ch) on E[ch&1]; energy(ch+1) -> E[(ch+1)&1].
// q,v triple-buffered via cp.async; v swizzled (stride 64, no pad).
#define FST 72   // k, q stride (halves)
#define EST 72   // E stride (halves)
#define K_OFF 0                           // 128*72 = 9216
#define E_OFF(p) (9216 + (p) * 9216)      // 2 x 128*72
#define Q_OFF(i) (27648 + (i) * 4608)     // 3 x 64*72
#define V_OFF(i) (41472 + (i) * 16384)    // 3 x 256*64 (swizzled)
#define TOT_H 90624                       // halves = 181248 B

__global__ __launch_bounds__(512, 1) void fused_attn(
    const __half* __restrict__ qg, const __half* __restrict__ kg,
    const __half* __restrict__ vg, const float* __restrict__ bgb,
    float* __restrict__ out) {
    extern __shared__ __half sm[];
    const int tid = threadIdx.x, lane = tid & 31, w = tid >> 5;
    const int m0 = blockIdx.x * 128, b = blockIdx.y;
    const uint32_t smb = smem_u32(sm);

    const __half* qgb = qg + (size_t)b * NPIX * CQK;
    const __half* vgb = vg + (size_t)b * CIN * NPIX;

    // ---- prologue: k tile + q(0) direct, then async groups 0,1
    {
        const uint4* kg4 = (const uint4*)(kg + ((size_t)b * NPIX + m0) * CQK);
#pragma unroll
        for (int it = 0; it < 2; it++) {
            int idx = tid + 512 * it;  // 1024 = 128 rows x 8
            int r = idx >> 3, s = idx & 7;
            *(uint4*)&sm[K_OFF + r * FST + s * 8] = kg4[idx];
        }
        const uint4* qg4 = (const uint4*)qgb;
        {
            int r = tid >> 3, s = tid & 7;  // 512 = 64 rows x 8
            *(uint4*)&sm[Q_OFF(0) + r * FST + s * 8] = qg4[tid];
        }
    }

    auto prefetch = [&](int i) {  // group i: v(i) -> V(i%3), q(i+1) -> Q((i+1)%3)
        const int n0 = i * 64;
        const uint32_t vdst = smb + V_OFF(i % 3) * 2;
#pragma unroll
        for (int it = 0; it < 4; it++) {
            int idx = tid + 512 * it;  // 2048 = 256 rows x 8
            int r = idx >> 3, s = idx & 7;
            CP_ASYNC16(vdst + (r * 64 + ((s ^ (r & 7)) * 8)) * 2,
                       vgb + (size_t)r * NPIX + n0 + s * 8);
        }
        if (i + 1 < NCH) {
            const uint32_t qdst = smb + Q_OFF((i + 1) % 3) * 2;
            int r = tid >> 3, s = tid & 7;
            CP_ASYNC16(qdst + (r * FST + s * 8) * 2,
                       qgb + (size_t)((i + 1) * 64 + r) * CQK + s * 8);
        }
        CP_COMMIT();
    };

    prefetch(0);
    prefetch(1);
    __syncthreads();  // k, q(0) visible

    const uint32_t ksb = smb + K_OFF * 2;
    const int wme = (w >> 1) * 16, wne = (w & 1) * 32;   // energy warp: 16m x 32n
    const int wc = (w >> 2) * 64, wm = (w & 3) * 32;     // AV warp: 64c x 32m

    // ---- energy(en): E[en&1](rows wme..+16, cols wne..+32) = elu(k.q(en)^T)
    auto energy = [&](int en) {
        const uint32_t qsb = smb + Q_OFF(en % 3) * 2;
        const uint32_t edst = smb + E_OFF(en & 1) * 2;
        float de[4][4] = {};
#pragma unroll
        for (int kk = 0; kk < 4; kk++) {
            const int ko = kk * 16;
            uint32_t a[4];
            {
                int row = wme + (lane & 7) + ((lane >> 3) & 1) * 8;
                int col = ko + (lane >> 4) * 8;
                ldsm_x4(a, ksb + (row * FST + col) * 2);
            }
#pragma unroll
            for (int g = 0; g < 2; g++) {
                uint32_t b4[4];
                int row = wne + g * 16 + (lane & 7) + (lane >> 4) * 8;
                int col = ko + ((lane >> 3) & 1) * 8;
                ldsm_x4(b4, qsb + (row * FST + col) * 2);
                mma16816(de[2 * g], a, b4);
                mma16816(de[2 * g + 1], a, b4 + 2);
            }
        }
        // elu -> fp16 -> E buffer
        const int m = wme + (lane >> 2);
        const int nb = wne + (lane & 3) * 2;
#pragma unroll
        for (int j = 0; j < 4; j++) {
            int col = nb + (j >> 1) * 16 + (j & 1) * 8;
            float* dd = de[j];
            asm volatile("st.shared.u32 [%0], %1;" ::
                         "r"(edst + (m * EST + col) * 2), "r"(elu2(dd[0], dd[1])));
            asm volatile("st.shared.u32 [%0], %1;" ::
                         "r"(edst + ((m + 8) * EST + col) * 2), "r"(elu2(dd[2], dd[3])));
        }
    };

    energy(0);

    float acc[4][4][4] = {};

    for (int ch = 0; ch < NCH; ch++) {
        if (ch >= NCH - 1) CP_WAIT(0); else CP_WAIT(1);
        __syncthreads();

        if (ch + 2 < NCH) prefetch(ch + 2);

        // ---- AV(ch): acc[c][m] += v . E^T
        {
            const uint32_t vsb = smb + V_OFF(ch % 3) * 2;
            const uint32_t esb = smb + E_OFF(ch & 1) * 2;
#pragma unroll
            for (int kk = 0; kk < 4; kk++) {
                const int ko = kk * 16;
                uint32_t a[4][4];
#pragma unroll
                for (int i = 0; i < 4; i++) {
                    int row = wc + i * 16 + (lane & 7) + ((lane >> 3) & 1) * 8;
                    int cnk = (ko >> 3) + (lane >> 4);
                    ldsm_x4(a[i], vsb + (row * 64 + ((cnk ^ (row & 7)) * 8)) * 2);
                }
#pragma unroll
                for (int g = 0; g < 2; g++) {
                    uint32_t b4[4];
                    int row = wm + g * 16 + (lane & 7) + (lane >> 4) * 8;
                    int col = ko + ((lane >> 3) & 1) * 8;
                    ldsm_x4(b4, esb + (row * EST + col) * 2);
#pragma unroll
                    for (int i = 0; i < 4; i++) {
                        mma16816(acc[i][2 * g], a[i], b4);
                        mma16816(acc[i][2 * g + 1], a[i], b4 + 2);
                    }
                }
            }
        }

        // ---- energy(ch+1) -> E[(ch+1)&1]
        if (ch + 1 < NCH) energy(ch + 1);
    }

    // ---- epilogue: /N + bias
    const float scale = 1.0f / (float)NPIX;
#pragma unroll
    for (int i = 0; i < 4; i++) {
        int c = wc + i * 16 + (lane >> 2);
        float b0 = bgb[c], b1 = bgb[c + 8];
#pragma unroll
        for (int j = 0; j < 4; j++) {
            int m = m0 + wm + (j >> 1) * 16 + (j & 1) * 8 + (lane & 3) * 2;
            float* dd = acc[i][j];
            *(float2*)&out[((size_t)b * CIN + c) * NPIX + m] =
                make_float2(dd[0] * scale + b0, dd[1] * scale + b0);
            *(float2*)&out[((size_t)b * CIN + c + 8) * NPIX + m] =
                make_float2(dd[2] * scale + b1, dd[3] * scale + b1);
        }
    }
}

// ------------------------------- launch -------------------------------------
extern "C" void kernel_launch(void* const* d_in, const int* in_sizes, int n_in,
                              void* d_out, int out_size) {
    const float* x  = (const float*)d_in[0];
    const float* wq = (const float*)d_in[1];
    const float* bq = (const float*)d_in[2];
    const float* wk = (const float*)d_in[3];
    const float* bk = (const float*)d_in[4];
    const float* wv = (const float*)d_in[5];
    const float* bv = (const float*)d_in[6];
    const float* wg = (const float*)d_in[7];
    const float* bg = (const float*)d_in[8];
    float* out = (float*)d_out;

    float *w2p, *bcp;
    __half *wcp, *qp, *kp, *vp;
    cudaGetSymbolAddress((void**)&w2p, g_w2);
    cudaGetSymbolAddress((void**)&wcp, g_wc);
    cudaGetSymbolAddress((void**)&bcp, g_bc);
    cudaGetSymbolAddress((void**)&qp, g_q);
    cudaGetSymbolAddress((void**)&kp, g_k);
    cudaGetSymbolAddress((void**)&vp, g_v);

    const int F_SMEM = TOT_H * (int)sizeof(__half);  // 181248
    cudaFuncSetAttribute(fused_attn, cudaFuncAttributeMaxDynamicSharedMemorySize, F_SMEM);

    fold_w<<<CIN, CIN>>>(wg, wv, w2p);
    pack_weights<<<384, CIN>>>(wq, wk, w2p, bq, bk, wg, bv, wcp, bcp);

    proj_qkv<<<dim3(3, NPIX / 128, BATCH), 256>>>(x, wcp, bcp, qp, kp, vp);

    fused_attn<<<dim3(NPIX / 128, BATCH), 512, F_SMEM>>>(qp, kp, vp, bg, out);
}

// round 12
// speedup vs baseline: 1.3114x; 1.0538x over previous
#include <cuda_runtime.h>
#include <cuda_fp16.h>
#include <cstdint>

#define NPIX 4096
#define CIN  256
#define CQK  64
#define BATCH 4
#define NCH  (NPIX / 64)

// ------------------------- device scratch ----------------------------------
__device__ float  g_w2[CIN * CIN];
__device__ __half g_wc[384 * CIN];
__device__ float  g_bc[384];
__device__ __half g_q[(size_t)BATCH * NPIX * CQK];   // [b][n][o]
__device__ __half g_k[(size_t)BATCH * NPIX * CQK];   // [b][m][o]
__device__ __half g_v[(size_t)BATCH * CIN * NPIX];   // [b][c][n]

// ------------------------- helpers -----------------------------------------
__device__ __forceinline__ uint32_t smem_u32(const void* p) {
    uint32_t a;
    asm("{ .reg .u64 t; cvta.to.shared.u64 t, %1; cvt.u32.u64 %0, t; }" : "=r"(a) : "l"(p));
    return a;
}
__device__ __forceinline__ void ldsm_x4(uint32_t a[4], uint32_t addr) {
    asm volatile("ldmatrix.sync.aligned.m8n8.x4.shared.b16 {%0,%1,%2,%3}, [%4];"
                 : "=r"(a[0]), "=r"(a[1]), "=r"(a[2]), "=r"(a[3]) : "r"(addr));
}
__device__ __forceinline__ void ldsm_x2(uint32_t a[2], uint32_t addr) {
    asm volatile("ldmatrix.sync.aligned.m8n8.x2.shared.b16 {%0,%1}, [%2];"
                 : "=r"(a[0]), "=r"(a[1]) : "r"(addr));
}
__device__ __forceinline__ void ldsm_x4_t(uint32_t a[4], uint32_t addr) {
    asm volatile("ldmatrix.sync.aligned.m8n8.x4.trans.shared.b16 {%0,%1,%2,%3}, [%4];"
                 : "=r"(a[0]), "=r"(a[1]), "=r"(a[2]), "=r"(a[3]) : "r"(addr));
}
__device__ __forceinline__ void ldsm_x2_t(uint32_t a[2], uint32_t addr) {
    asm volatile("ldmatrix.sync.aligned.m8n8.x2.trans.shared.b16 {%0,%1}, [%2];"
                 : "=r"(a[0]), "=r"(a[1]) : "r"(addr));
}
__device__ __forceinline__ void mma16816(float d[4], const uint32_t a[4], const uint32_t* b) {
    asm volatile(
        "mma.sync.aligned.m16n8k16.row.col.f32.f16.f16.f32 "
        "{%0,%1,%2,%3}, {%4,%5,%6,%7}, {%8,%9}, {%0,%1,%2,%3};"
        : "+f"(d[0]), "+f"(d[1]), "+f"(d[2]), "+f"(d[3])
        : "r"(a[0]), "r"(a[1]), "r"(a[2]), "r"(a[3]), "r"(b[0]), "r"(b[1]));
}
#define CP_ASYNC16(dst, src) \
    asm volatile("cp.async.cg.shared.global [%0], [%1], 16;" :: "r"(dst), "l"(src))
#define CP_COMMIT() asm volatile("cp.async.commit_group;" ::: "memory")
#define CP_WAIT(n)  asm volatile("cp.async.wait_group %0;" :: "n"(n) : "memory")

__device__ __forceinline__ unsigned pk2(float a, float b) {
    __half2 h = __floats2half2_rn(a, b);
    return *(unsigned*)&h;
}
// elu on a packed fp16x2 pair: x>0 ? x : exp(x)-1, one MUFU per 2 values
__device__ __forceinline__ unsigned elu2(float x0, float x1) {
    __half2 h = __floats2half2_rn(x0, x1);
    __half2 hl = __hmul2(h, __float2half2_rn(1.44269504f));
    unsigned eu;
    asm("ex2.approx.f16x2 %0, %1;" : "=r"(eu) : "r"(*(unsigned*)&hl));
    __half2 em1 = __hsub2(*(__half2*)&eu, __float2half2_rn(1.0f));
    __half2 mask = __hgt2(h, __float2half2_rn(0.0f));
    __half2 r = __hfma2(mask, __hsub2(h, em1), em1);
    return *(unsigned*)&r;
}

// ------------------------- weight folding / packing ------------------------
__global__ void fold_w(const float* __restrict__ wg, const float* __restrict__ wv,
                       float* __restrict__ w2) {
    int o = blockIdx.x, j = threadIdx.x;
    float s = 0.f;
    for (int c = 0; c < CIN; c++) s += wg[o * CIN + c] * wv[c * CIN + j];
    w2[o * CIN + j] = s;
}
__global__ void pack_weights(const float* __restrict__ wq, const float* __restrict__ wk,
                             const float* __restrict__ w2, const float* __restrict__ bq,
                             const float* __restrict__ bk, const float* __restrict__ wg,
                             const float* __restrict__ bv, __half* __restrict__ Wc,
                             float* __restrict__ bc) {
    int r = blockIdx.x, c = threadIdx.x;
    const float* src = r < 64 ? wq + r * CIN : (r < 128 ? wk + (r - 64) * CIN : w2 + (r - 128) * CIN);
    Wc[r * CIN + c] = __float2half(src[c]);
    if (c == 0) {
        if (r < 64) bc[r] = bq[r];
        else if (r < 128) bc[r] = bk[r - 64];
        else {
            float s = 0.f;
            int o = r - 128;
            for (int cc = 0; cc < CIN; cc++) s += wg[o * CIN + cc] * bv[cc];
            bc[r] = s;
        }
    }
}

// ----------------- fused QKV projection (HMMA, fp16) -----------------------
#define XST 136
#define WST 72

__global__ __launch_bounds__(256) void proj_qkv(
    const float* __restrict__ X, const __half* __restrict__ Wc,
    const float* __restrict__ bc, __half* __restrict__ qout,
    __half* __restrict__ kout, __half* __restrict__ vout) {
    __shared__ __align__(16) __half XT[64 * XST];
    __shared__ __align__(16) __half WT[128 * WST];
    const int tid = threadIdx.x, lane = tid & 31, w = tid >> 5;
    const int wtile = blockIdx.x, n0 = blockIdx.y * 128, b = blockIdx.z;
    const float* Xb = X + (size_t)b * CIN * NPIX;
    const __half* Wrow = Wc + (size_t)wtile * 128 * CIN;

    const int wa = (w >> 2) * 64, wb = (w & 3) * 32;
    const uint32_t XTb = smem_u32(XT), WTb = smem_u32(WT);
    float d[4][4][4] = {};

    for (int ck = 0; ck < 4; ck++) {
        const int c0 = ck * 64;
#pragma unroll
        for (int it = 0; it < 8; it++) {
            int idx = it * 256 + tid;
            int cc = idx >> 5, ng = idx & 31;
            float4 x4 = *(const float4*)&Xb[(size_t)(c0 + cc) * NPIX + n0 + ng * 4];
            uint2 u;
            u.x = pk2(x4.x, x4.y);
            u.y = pk2(x4.z, x4.w);
            *(uint2*)&XT[cc * XST + ng * 4] = u;
        }
#pragma unroll
        for (int it = 0; it < 4; it++) {
            int idx = it * 256 + tid;
            int r = idx >> 3, g = idx & 7;
            *(uint4*)&WT[r * WST + g * 8] = *(const uint4*)&Wrow[(size_t)r * CIN + c0 + g * 8];
        }
        __syncthreads();

        if (wtile == 0) {
#pragma unroll
            for (int kk = 0; kk < 4; kk++) {
                const int kofs = kk * 16;
                uint32_t a[4][4], bb[4][2];
#pragma unroll
                for (int i = 0; i < 4; i++) {
                    int rc = kofs + (lane & 7) + (lane >> 4) * 8;
                    int cn = wa + i * 16 + ((lane >> 3) & 1) * 8;
                    ldsm_x4_t(a[i], XTb + (rc * XST + cn) * 2);
                }
#pragma unroll
                for (int j = 0; j < 4; j++) {
                    int l = lane & 15;
                    int row = wb + j * 8 + (l & 7);
                    int col = kofs + (l >> 3) * 8;
                    ldsm_x2(bb[j], WTb + (row * WST + col) * 2);
                }
#pragma unroll
                for (int i = 0; i < 4; i++)
#pragma unroll
                    for (int j = 0; j < 4; j++) mma16816(d[i][j], a[i], bb[j]);
            }
        } else {
#pragma unroll
            for (int kk = 0; kk < 4; kk++) {
                const int kofs = kk * 16;
                uint32_t a[4][4], bb[4][2];
#pragma unroll
                for (int i = 0; i < 4; i++) {
                    int row = wa + i * 16 + (lane & 7) + ((lane >> 3) & 1) * 8;
                    int col = kofs + (lane >> 4) * 8;
                    ldsm_x4(a[i], WTb + (row * WST + col) * 2);
                }
#pragma unroll
                for (int j = 0; j < 4; j++) {
                    int l = lane & 15;
                    int rc = kofs + l;
                    int cn = wb + j * 8;
                    ldsm_x2_t(bb[j], XTb + (rc * XST + cn) * 2);
                }
#pragma unroll
                for (int i = 0; i < 4; i++)
#pragma unroll
                    for (int j = 0; j < 4; j++) mma16816(d[i][j], a[i], bb[j]);
            }
        }
        __syncthreads();
    }

    if (wtile == 0) {
#pragma unroll
        for (int j = 0; j < 4; j++) {
            int o = wb + j * 8 + (lane & 3) * 2;
            float b0 = bc[o], b1 = bc[o + 1];
            __half* dst = o < 64 ? qout : kout;
            int oo = o < 64 ? o : o - 64;
#pragma unroll
            for (int i = 0; i < 4; i++) {
                int n = n0 + wa + i * 16 + (lane >> 2);
                float* dd = d[i][j];
                *(unsigned*)&dst[((size_t)b * NPIX + n) * CQK + oo] = pk2(dd[0] + b0, dd[1] + b1);
                *(unsigned*)&dst[((size_t)b * NPIX + n + 8) * CQK + oo] = pk2(dd[2] + b0, dd[3] + b1);
            }
        }
    } else {
#pragma unroll
        for (int i = 0; i < 4; i++) {
            int c = (wtile - 1) * 128 + wa + i * 16 + (lane >> 2);
            float b0 = bc[128 + c], b1 = bc[128 + c + 8];
#pragma unroll
            for (int j = 0; j < 4; j++) {
                int n = n0 + wb + j * 8 + (lane & 3) * 2;
                float* dd = d[i][j];
                *(unsigned*)&vout[((size_t)b * CIN + c) * NPIX + n] = pk2(dd[0] + b0, dd[1] + b0);
                *(unsigned*)&vout[((size_t)b * CIN + c + 8) * NPIX + n] = pk2(dd[2] + b1, dd[3] + b1);
            }
        }
    }
}

// ------ fused attention: warp-specialized pipelined energy + AV ------------
// CTA = (m-tile 128, batch), 384 thr. Warps 0-7: AV (64c x 64m each);
// warps 8-11: energy (32m x 64n each, k fragments register-resident).
// Per chunk: one __syncthreads; AV(ch) reads E[ch&1] while energy writes E[(ch+1)&1].
#define FST 72   // k, q stride (halves)
#define EST 72   // E stride (halves)
#define K_OFF 0                           // 128*72 = 9216
#define E_OFF(p) (9216 + (p) * 9216)      // 2 x 128*72
#define Q_OFF(i) (27648 + (i) * 4608)     // 3 x 64*72
#define V_OFF(i) (41472 + (i) * 16384)    // 3 x 256*64 (swizzled)
#define TOT_H 90624                       // halves = 181248 B

__global__ __launch_bounds__(384, 1) void fused_attn(
    const __half* __restrict__ qg, const __half* __restrict__ kg,
    const __half* __restrict__ vg, const float* __restrict__ bgb,
    float* __restrict__ out) {
    extern __shared__ __half sm[];
    const int tid = threadIdx.x, lane = tid & 31, w = tid >> 5;
    const int m0 = blockIdx.x * 128, b = blockIdx.y;
    const uint32_t smb = smem_u32(sm);

    const __half* qgb = qg + (size_t)b * NPIX * CQK;
    const __half* vgb = vg + (size_t)b * CIN * NPIX;

    // ---- prologue: k (tid<256) + q(0) (tid>=256) direct loads
    if (tid < 256) {
        const uint4* kg4 = (const uint4*)(kg + ((size_t)b * NPIX + m0) * CQK);
#pragma unroll
        for (int it = 0; it < 4; it++) {
            int idx = tid + 256 * it;  // 1024 = 128 rows x 8
            int r = idx >> 3, s = idx & 7;
            *(uint4*)&sm[K_OFF + r * FST + s * 8] = kg4[idx];
        }
    } else {
        const uint4* qg4 = (const uint4*)qgb;
        int t = tid - 256;
#pragma unroll
        for (int it = 0; it < 4; it++) {
            int idx = t + 128 * it;  // 512 = 64 rows x 8
            int r = idx >> 3, s = idx & 7;
            *(uint4*)&sm[Q_OFF(0) + r * FST + s * 8] = qg4[idx];
        }
    }

    // group i: v(i) -> V(i%3) [if valid], q(i+1) -> Q((i+1)%3) [if valid].
    // ALWAYS commits exactly one group (accounting), even when empty.
    auto prefetch = [&](int i) {
        if (tid < 256) {
            if (i < NCH) {
                const int n0 = i * 64;
                const uint32_t vdst = smb + V_OFF(i % 3) * 2;
#pragma unroll
                for (int it = 0; it < 8; it++) {
                    int idx = tid + 256 * it;  // 2048 = 256 rows x 8
                    int r = idx >> 3, s = idx & 7;
                    CP_ASYNC16(vdst + (r * 64 + ((s ^ (r & 7)) * 8)) * 2,
                               vgb + (size_t)r * NPIX + n0 + s * 8);
                }
            }
        } else if (i + 1 < NCH) {
            const uint32_t qdst = smb + Q_OFF((i + 1) % 3) * 2;
            int t = tid - 256;
#pragma unroll
            for (int it = 0; it < 4; it++) {
                int idx = t + 128 * it;
                int r = idx >> 3, s = idx & 7;
                CP_ASYNC16(qdst + (r * FST + s * 8) * 2,
                           qgb + (size_t)((i + 1) * 64 + r) * CQK + s * 8);
            }
        }
        CP_COMMIT();
    };

    prefetch(0);
    prefetch(1);
    __syncthreads();  // k, q(0) visible

    const uint32_t ksb = smb + K_OFF * 2;

    if (w >= 8) {
        // =================== ENERGY WARPS (4) ===================
        const int ew = w - 8;
        const int wme = ew * 32;  // 32 m-rows per warp

        // k fragments register-resident: [kk][i]
        uint32_t kfr[4][2][4];
#pragma unroll
        for (int kk = 0; kk < 4; kk++)
#pragma unroll
            for (int i = 0; i < 2; i++) {
                int row = wme + i * 16 + (lane & 7) + ((lane >> 3) & 1) * 8;
                int col = kk * 16 + (lane >> 4) * 8;
                ldsm_x4(kfr[kk][i], ksb + (row * FST + col) * 2);
            }

        auto energy = [&](int en) {
            const uint32_t qsb = smb + Q_OFF(en % 3) * 2;
            const uint32_t edst = smb + E_OFF(en & 1) * 2;
            float de[2][8][4] = {};
#pragma unroll
            for (int kk = 0; kk < 4; kk++) {
                const int ko = kk * 16;
#pragma unroll
                for (int jj = 0; jj < 4; jj++) {
                    uint32_t b4[4];
                    int row = jj * 16 + (lane & 7) + (lane >> 4) * 8;
                    int col = ko + ((lane >> 3) & 1) * 8;
                    ldsm_x4(b4, qsb + (row * FST + col) * 2);
#pragma unroll
                    for (int i = 0; i < 2; i++) {
                        mma16816(de[i][2 * jj], kfr[kk][i], b4);
                        mma16816(de[i][2 * jj + 1], kfr[kk][i], b4 + 2);
                    }
                }
            }
            const int m = wme + (lane >> 2);
            const int nb = (lane & 3) * 2;
#pragma unroll
            for (int i = 0; i < 2; i++)
#pragma unroll
                for (int j = 0; j < 8; j++) {
                    int col = nb + j * 8;
                    float* dd = de[i][j];
                    asm volatile("st.shared.u32 [%0], %1;" ::
                                 "r"(edst + ((m + i * 16) * EST + col) * 2),
                                 "r"(elu2(dd[0], dd[1])));
                    asm volatile("st.shared.u32 [%0], %1;" ::
                                 "r"(edst + ((m + i * 16 + 8) * EST + col) * 2),
                                 "r"(elu2(dd[2], dd[3])));
                }
        };

        energy(0);  // prologue: E[0]

        for (int ch = 0; ch < NCH; ch++) {
            if (ch >= NCH - 1) CP_WAIT(0); else CP_WAIT(1);
            __syncthreads();
            prefetch(ch + 2);
            if (ch + 1 < NCH) energy(ch + 1);
        }
    } else {
        // =================== AV WARPS (8) ===================
        const int wc = (w >> 1) * 64, wm = (w & 1) * 64;
        float acc[4][8][4] = {};

        for (int ch = 0; ch < NCH; ch++) {
            if (ch >= NCH - 1) CP_WAIT(0); else CP_WAIT(1);
            __syncthreads();
            prefetch(ch + 2);

            const uint32_t vsb = smb + V_OFF(ch % 3) * 2;
            const uint32_t esb = smb + E_OFF(ch & 1) * 2;
#pragma unroll
            for (int kk = 0; kk < 4; kk++) {
                const int ko = kk * 16;
                uint32_t a[4][4];
#pragma unroll
                for (int i = 0; i < 4; i++) {
                    int row = wc + i * 16 + (lane & 7) + ((lane >> 3) & 1) * 8;
                    int cnk = (ko >> 3) + (lane >> 4);
                    ldsm_x4(a[i], vsb + (row * 64 + ((cnk ^ (row & 7)) * 8)) * 2);
                }
#pragma unroll
                for (int jj = 0; jj < 4; jj++) {
                    uint32_t b4[4];
                    int row = wm + jj * 16 + (lane & 7) + (lane >> 4) * 8;
                    int col = ko + ((lane >> 3) & 1) * 8;
                    ldsm_x4(b4, esb + (row * EST + col) * 2);
#pragma unroll
                    for (int i = 0; i < 4; i++) {
                        mma16816(acc[i][2 * jj], a[i], b4);
                        mma16816(acc[i][2 * jj + 1], a[i], b4 + 2);
                    }
                }
            }
        }

        // ---- epilogue: /N + bias (AV warps only)
        const float scale = 1.0f / (float)NPIX;
#pragma unroll
        for (int i = 0; i < 4; i++) {
            int c = wc + i * 16 + (lane >> 2);
            float b0 = bgb[c], b1 = bgb[c + 8];
#pragma unroll
            for (int j = 0; j < 8; j++) {
                int m = m0 + wm + j * 8 + (lane & 3) * 2;
                float* dd = acc[i][j];
                *(float2*)&out[((size_t)b * CIN + c) * NPIX + m] =
                    make_float2(dd[0] * scale + b0, dd[1] * scale + b0);
                *(float2*)&out[((size_t)b * CIN + c + 8) * NPIX + m] =
                    make_float2(dd[2] * scale + b1, dd[3] * scale + b1);
            }
        }
    }
}

// ------------------------------- launch -------------------------------------
extern "C" void kernel_launch(void* const* d_in, const int* in_sizes, int n_in,
                              void* d_out, int out_size) {
    const float* x  = (const float*)d_in[0];
    const float* wq = (const float*)d_in[1];
    const float* bq = (const float*)d_in[2];
    const float* wk = (const float*)d_in[3];
    const float* bk = (const float*)d_in[4];
    const float* wv = (const float*)d_in[5];
    const float* bv = (const float*)d_in[6];
    const float* wg = (const float*)d_in[7];
    const float* bg = (const float*)d_in[8];
    float* out = (float*)d_out;

    float *w2p, *bcp;
    __half *wcp, *qp, *kp, *vp;
    cudaGetSymbolAddress((void**)&w2p, g_w2);
    cudaGetSymbolAddress((void**)&wcp, g_wc);
    cudaGetSymbolAddress((void**)&bcp, g_bc);
    cudaGetSymbolAddress((void**)&qp, g_q);
    cudaGetSymbolAddress((void**)&kp, g_k);
    cudaGetSymbolAddress((void**)&vp, g_v);

    const int F_SMEM = TOT_H * (int)sizeof(__half);  // 181248
    cudaFuncSetAttribute(fused_attn, cudaFuncAttributeMaxDynamicSharedMemorySize, F_SMEM);

    fold_w<<<CIN, CIN>>>(wg, wv, w2p);
    pack_weights<<<384, CIN>>>(wq, wk, w2p, bq, bk, wg, bv, wcp, bcp);

    proj_qkv<<<dim3(3, NPIX / 128, BATCH), 256>>>(x, wcp, bcp, qp, kp, vp);

    fused_attn<<<dim3(NPIX / 128, BATCH), 384, F_SMEM>>>(qp, kp, vp, bg, out);
}